// round 17
// baseline (speedup 1.0000x reference)
#include <cuda_runtime.h>
#include <cuda_bf16.h>
#include <cuda_fp16.h>
#include <cstdint>
#include <cstddef>

// ---------------------------------------------------------------------------
// multilayer_message_passing: 2-layer hetero GraphSAGE.
// R17: R16 base (481us). Pull gathers from fp16 mirror tables (halves L2
//      traffic; fp32 accumulate). Mirrors: inputs converted once; update
//      epilogue writes fp16 alongside fp32 (skipped on last layer).
// ---------------------------------------------------------------------------

#define N_GENE_MAX 100000
#define N_DIS_MAX   50000
#define DIM 128
#define E_MAX 800000
#define SCAN_TILE 4096

__device__ float g_agg_d[(size_t)N_DIS_MAX  * DIM];
__device__ float g_agg_g[(size_t)N_GENE_MAX * DIM];
__device__ __align__(16) __half g_xh_g[(size_t)N_GENE_MAX * DIM];  // fp16 mirror (gene)
__device__ __align__(16) __half g_xh_d[(size_t)N_DIS_MAX  * DIM]; // fp16 mirror (disease)
__device__ int g_cnt_d[N_DIS_MAX];
__device__ int g_cnt_g[N_GENE_MAX];
__device__ int g_off_d[N_DIS_MAX + 1];
__device__ int g_off_g[N_GENE_MAX + 1];
__device__ int g_cur_d[N_DIS_MAX];
__device__ int g_cur_g[N_GENE_MAX];
__device__ int g_csr_g2d[E_MAX];
__device__ int g_csr_d2g[E_MAX];
__device__ int g_tmp[N_DIS_MAX + N_GENE_MAX];
__device__ int g_part[128];
__device__ __align__(16) __nv_bfloat16 g_wimg[16][DIM * DIM];

// ---------------------------------------------------------------------------
__device__ __forceinline__ uint32_t smem_u32(const void* p) {
    uint32_t a;
    asm("{ .reg .u64 t; cvta.to.shared.u64 t, %1; cvt.u32.u64 %0, t; }" : "=r"(a) : "l"(p));
    return a;
}

#define LDMX4(r, addr)                                                         \
    asm volatile("ldmatrix.sync.aligned.m8n8.x4.shared.b16 {%0,%1,%2,%3}, [%4];" \
                 : "=r"((r)[0]), "=r"((r)[1]), "=r"((r)[2]), "=r"((r)[3])      \
                 : "r"(addr))

#define MMA16816(d, a, b0, b1)                                                 \
    asm volatile("mma.sync.aligned.m16n8k16.row.col.f32.bf16.bf16.f32 "        \
                 "{%0,%1,%2,%3}, {%4,%5,%6,%7}, {%8,%9}, {%0,%1,%2,%3};"       \
                 : "+f"((d)[0]), "+f"((d)[1]), "+f"((d)[2]), "+f"((d)[3])      \
                 : "r"((a)[0]), "r"((a)[1]), "r"((a)[2]), "r"((a)[3]),         \
                   "r"(b0), "r"(b1))

// ---------------------------------------------------------------------------
// CSR build
// ---------------------------------------------------------------------------
__global__ void zero2_kernel(int* __restrict__ a, int na, int* __restrict__ b, int nb) {
    int i = blockIdx.x * blockDim.x + threadIdx.x;
    if (i < na) a[i] = 0;
    if (i < nb) b[i] = 0;
}

__global__ void count2_kernel(const int* __restrict__ dst1, int* __restrict__ cnt1, int E1,
                              const int* __restrict__ dst2, int* __restrict__ cnt2, int E2) {
    int e = blockIdx.x * blockDim.x + threadIdx.x;
    if (e < E1) atomicAdd(&cnt1[dst1[e]], 1);
    else if (e < E1 + E2) atomicAdd(&cnt2[dst2[e - E1]], 1);
}

__global__ void __launch_bounds__(1024)
scan_p1_kernel(const int* __restrict__ cnt_d, int n_dis,
               const int* __restrict__ cnt_g, int n_gene,
               int* __restrict__ tmp, int* __restrict__ part) {
    __shared__ int wsum[32];
    const int n_tot = n_dis + n_gene;
    const int t = threadIdx.x, lane = t & 31, wid = t >> 5;
    const int base = blockIdx.x * SCAN_TILE + t * 4;

    int v[4];
#pragma unroll
    for (int j = 0; j < 4; j++) {
        int i = base + j;
        v[j] = (i < n_tot) ? (i < n_dis ? cnt_d[i] : cnt_g[i - n_dis]) : 0;
    }
    int tsum = v[0] + v[1] + v[2] + v[3];
    int x = tsum;
#pragma unroll
    for (int o = 1; o < 32; o <<= 1) {
        int y = __shfl_up_sync(0xffffffffu, x, o);
        if (lane >= o) x += y;
    }
    if (lane == 31) wsum[wid] = x;
    __syncthreads();
    if (wid == 0) {
        int s = wsum[lane];
#pragma unroll
        for (int o = 1; o < 32; o <<= 1) {
            int y = __shfl_up_sync(0xffffffffu, s, o);
            if (lane >= o) s += y;
        }
        wsum[lane] = s;
    }
    __syncthreads();
    int ex = (x - tsum) + (wid > 0 ? wsum[wid - 1] : 0);
#pragma unroll
    for (int j = 0; j < 4; j++) {
        int i = base + j;
        if (i < n_tot) tmp[i] = ex;
        ex += v[j];
    }
    if (t == 1023) part[blockIdx.x] = wsum[31];
}

__global__ void scan_p3_kernel(const int* __restrict__ tmp, const int* __restrict__ part,
                               int nb,
                               int* __restrict__ off_d, int* __restrict__ cur_d, int n_dis,
                               int* __restrict__ off_g, int* __restrict__ cur_g, int n_gene,
                               int E1, int E2) {
    __shared__ int spref[128];
    const int t = threadIdx.x;
    if (t == 0) {
        int c = 0;
        for (int q = 0; q < nb; q++) { spref[q] = c; c += part[q]; }
    }
    __syncthreads();

    int i = blockIdx.x * blockDim.x + t;
    int n_tot = n_dis + n_gene;
    if (i < n_tot) {
        int ex = tmp[i] + spref[i >> 12];
        if (i < n_dis) { off_d[i] = ex; cur_d[i] = ex; }
        else { int k = i - n_dis; int e = ex - E1; off_g[k] = e; cur_g[k] = e; }
    }
    if (i == 0) { off_d[n_dis] = E1; off_g[n_gene] = E2; }
}

__global__ void fill2_kernel(const int* __restrict__ src1, const int* __restrict__ dst1,
                             int* __restrict__ cur1, int* __restrict__ csr1, int E1,
                             const int* __restrict__ src2, const int* __restrict__ dst2,
                             int* __restrict__ cur2, int* __restrict__ csr2, int E2) {
    int e = blockIdx.x * blockDim.x + threadIdx.x;
    if (e < E1) {
        int p = atomicAdd(&cur1[dst1[e]], 1);
        csr1[p] = src1[e];
    } else if (e < E1 + E2) {
        int i = e - E1;
        int p = atomicAdd(&cur2[dst2[i]], 1);
        csr2[p] = src2[i];
    }
}

// convert fp32 input tables -> fp16 mirrors (layer-0 gather source)
__global__ void prep_xh_kernel(const float* __restrict__ xg, __half* __restrict__ xh_g,
                               size_t ng_el,
                               const float* __restrict__ xd, __half* __restrict__ xh_d,
                               size_t nd_el) {
    size_t i4 = ((size_t)blockIdx.x * blockDim.x + threadIdx.x);
    size_t tot4 = (ng_el + nd_el) >> 2;
    size_t stride = (size_t)gridDim.x * blockDim.x;
    for (; i4 < tot4; i4 += stride) {
        const float4* src;
        __half* dst;
        size_t o4;
        if (i4 < (ng_el >> 2)) { src = (const float4*)xg; dst = xh_g; o4 = i4; }
        else { src = (const float4*)xd; dst = xh_d; o4 = i4 - (ng_el >> 2); }
        float4 v = src[o4];
        __half2 p0 = __floats2half2_rn(v.x, v.y);
        __half2 p1 = __floats2half2_rn(v.z, v.w);
        uint2 pk;
        pk.x = *(uint32_t*)&p0;
        pk.y = *(uint32_t*)&p1;
        *(uint2*)(dst + o4 * 4) = pk;
    }
}

// ---------------------------------------------------------------------------
// fused pull (frozen structure): warp per dst node; gathers fp16 (uint2/lane),
// fp32 accumulate. Traffic halved vs fp32 gather.
// ---------------------------------------------------------------------------
__global__ void __launch_bounds__(256)
pull_fused_kernel(const __half* __restrict__ xg_h, const __half* __restrict__ xd_h,
                  float* __restrict__ agg_d, float* __restrict__ agg_g,
                  const int* __restrict__ csr_g2d, const int* __restrict__ off_d,
                  const int* __restrict__ csr_d2g, const int* __restrict__ off_g,
                  int n_dis, int n_gene) {
    const int w = (blockIdx.x * blockDim.x + threadIdx.x) >> 5;
    const int lane = threadIdx.x & 31;
    const uint2* __restrict__ base;
    const int* __restrict__ csr;
    const int* __restrict__ off;
    float* aggp;
    int node;
    if (w < n_dis) {
        node = w; base = (const uint2*)xg_h; csr = csr_g2d; off = off_d;
        aggp = agg_d;
    } else if (w < n_dis + n_gene) {
        node = w - n_dis; base = (const uint2*)xd_h; csr = csr_d2g; off = off_g;
        aggp = agg_g;
    } else return;

    const int start = off[node], end = off[node + 1];
    float4 acc0 = make_float4(0.f, 0.f, 0.f, 0.f);
    float4 acc1 = make_float4(0.f, 0.f, 0.f, 0.f);

#define ACCUM(ACC, RAW)                                                        \
    do {                                                                       \
        float2 f0_ = __half22float2(*(__half2*)&(RAW).x);                      \
        float2 f1_ = __half22float2(*(__half2*)&(RAW).y);                      \
        (ACC).x += f0_.x; (ACC).y += f0_.y; (ACC).z += f1_.x; (ACC).w += f1_.y;\
    } while (0)

    int e = start;
    for (; e + 8 <= end; e += 8) {
        int s0 = csr[e],     s1 = csr[e + 1], s2 = csr[e + 2], s3 = csr[e + 3];
        int s4 = csr[e + 4], s5 = csr[e + 5], s6 = csr[e + 6], s7 = csr[e + 7];
        uint2 a = base[(size_t)s0 * 32 + lane];
        uint2 b = base[(size_t)s1 * 32 + lane];
        uint2 c = base[(size_t)s2 * 32 + lane];
        uint2 d = base[(size_t)s3 * 32 + lane];
        uint2 p = base[(size_t)s4 * 32 + lane];
        uint2 q = base[(size_t)s5 * 32 + lane];
        uint2 r = base[(size_t)s6 * 32 + lane];
        uint2 s = base[(size_t)s7 * 32 + lane];
        ACCUM(acc0, a); ACCUM(acc0, b);
        ACCUM(acc1, c); ACCUM(acc1, d);
        ACCUM(acc0, p); ACCUM(acc0, q);
        ACCUM(acc1, r); ACCUM(acc1, s);
    }
    for (; e + 2 <= end; e += 2) {
        uint2 a = base[(size_t)csr[e] * 32 + lane];
        uint2 b = base[(size_t)csr[e + 1] * 32 + lane];
        ACCUM(acc0, a); ACCUM(acc1, b);
    }
    if (e < end) {
        uint2 a = base[(size_t)csr[e] * 32 + lane];
        ACCUM(acc0, a);
    }
#undef ACCUM

    float inv = 1.0f / fmaxf((float)(end - start), 1.0f);
    float4 o;
    o.x = (acc0.x + acc1.x) * inv;
    o.y = (acc0.y + acc1.y) * inv;
    o.z = (acc0.z + acc1.z) * inv;
    o.w = (acc0.w + acc1.w) * inv;
    ((float4*)aggp)[(size_t)node * 32 + lane] = o;
}

// bf16 hi/lo images of all 8 weight matrices (plain row-major)
__global__ void prep_w_kernel(const float* __restrict__ Wl, const float* __restrict__ Wr) {
    int mat = blockIdx.x;
    int lt = mat >> 1, which = mat & 1;
    const float* W = (which ? Wr : Wl) + (size_t)lt * DIM * DIM;
    __nv_bfloat16* ih = g_wimg[mat * 2 + 0];
    __nv_bfloat16* il = g_wimg[mat * 2 + 1];
    for (int i = threadIdx.x; i < DIM * DIM; i += blockDim.x) {
        float w = W[i];
        __nv_bfloat16 h = __float2bfloat16(w);
        ih[i] = h;
        il[i] = __float2bfloat16(w - __bfloat162float(h));
    }
}

// ---------------------------------------------------------------------------
// fused update, TM=64 (105KB smem -> 2 CTA/SM), R16 staging. R17 delta:
// epilogue also writes fp16 mirror (when write_h != 0).
// ---------------------------------------------------------------------------
#define TM       64
#define ZSTRIDE  136
#define ZT_B     (TM * ZSTRIDE * 2)
#define WT_B     (DIM * ZSTRIDE * 2)
#define OFF_BIAS 0
#define OFF_ZH   1024
#define OFF_ZL   (OFF_ZH + ZT_B)
#define OFF_WH   (OFF_ZL + ZT_B)
#define OFF_WL   (OFF_WH + WT_B)
#define SMEM_TOT (OFF_WL + WT_B)
#define HSTRIDE  132

__global__ void __launch_bounds__(256)
update_fused_kernel(const float* __restrict__ agg_d, const float* __restrict__ xin_d,
                    float* __restrict__ xout_d, __half* __restrict__ xh_d, int n_d,
                    const float* __restrict__ agg_g, const float* __restrict__ xin_g,
                    float* __restrict__ xout_g, __half* __restrict__ xh_g, int n_g,
                    const __nv_bfloat16* __restrict__ wimg, const float* __restrict__ bias_base,
                    int layer, int nbd, int do_relu, int write_h) {
    extern __shared__ __align__(16) unsigned char smem[];
    const uint32_t sbase = smem_u32(smem);
    const int t    = threadIdx.x;
    const int wid  = t >> 5;
    const int lane = t & 31;
    const int wm   = wid >> 2;
    const int wn   = wid & 3;
    const int r0   = wm * 32;

    const int is_g = (blockIdx.x >= nbd) ? 1 : 0;
    const int tile = (is_g ? (blockIdx.x - nbd) : blockIdx.x) * TM;
    const float* agg  = is_g ? agg_g : agg_d;
    const float* xin  = is_g ? xin_g : xin_d;
    float*       xout = is_g ? xout_g : xout_d;
    __half*      xh   = is_g ? xh_g : xh_d;
    const int n = is_g ? n_g : n_d;
    const int lt = layer * 2 + is_g;
    const __nv_bfloat16* wl_hi = wimg + (size_t)(lt * 4 + 0) * DIM * DIM;
    const __nv_bfloat16* wl_lo = wimg + (size_t)(lt * 4 + 1) * DIM * DIM;
    const __nv_bfloat16* wr_hi = wimg + (size_t)(lt * 4 + 2) * DIM * DIM;
    const __nv_bfloat16* wr_lo = wimg + (size_t)(lt * 4 + 3) * DIM * DIM;
    const float* bias = bias_base + (size_t)lt * DIM;

    float* sbias = (float*)(smem + OFF_BIAS);
    if (t < 128) sbias[t] = bias[t];

    const uint32_t aoff =
        ((uint32_t)((r0 + ((lane >> 3) & 1) * 8 + (lane & 7)) * ZSTRIDE +
                    ((lane >> 4) & 1) * 8)) * 2;
    const uint32_t boff =
        ((uint32_t)((wn * 32 + ((lane >> 4) & 1) * 8 + (lane & 7)) * ZSTRIDE +
                    ((lane >> 3) & 1) * 8)) * 2;

    float acc[2][4][4];
#pragma unroll
    for (int f = 0; f < 2; f++)
#pragma unroll
        for (int j = 0; j < 4; j++)
#pragma unroll
            for (int c = 0; c < 4; c++) acc[f][j][c] = 0.0f;

    __nv_bfloat16* zh = (__nv_bfloat16*)(smem + OFF_ZH);
    __nv_bfloat16* zl = (__nv_bfloat16*)(smem + OFF_ZL);

    for (int phase = 0; phase < 2; phase++) {
        {
            const float* zsrc = (phase == 0) ? agg : xin;
            const float4* z4 = (const float4*)zsrc + (size_t)tile * 32;
            for (int i = t; i < TM * 32; i += 256) {
                int row = i >> 5, c4 = i & 31;
                float4 v = make_float4(0.f, 0.f, 0.f, 0.f);
                if (tile + row < n) v = z4[(size_t)row * 32 + c4];
                __nv_bfloat16 h0 = __float2bfloat16(v.x);
                __nv_bfloat16 h1 = __float2bfloat16(v.y);
                __nv_bfloat16 h2 = __float2bfloat16(v.z);
                __nv_bfloat16 h3 = __float2bfloat16(v.w);
                __nv_bfloat162 hp0; hp0.x = h0; hp0.y = h1;
                __nv_bfloat162 hp1; hp1.x = h2; hp1.y = h3;
                __nv_bfloat162 lp0;
                lp0.x = __float2bfloat16(v.x - __bfloat162float(h0));
                lp0.y = __float2bfloat16(v.y - __bfloat162float(h1));
                __nv_bfloat162 lp1;
                lp1.x = __float2bfloat16(v.z - __bfloat162float(h2));
                lp1.y = __float2bfloat16(v.w - __bfloat162float(h3));
                __nv_bfloat16* zhp = zh + row * ZSTRIDE + c4 * 4;
                __nv_bfloat16* zlp = zl + row * ZSTRIDE + c4 * 4;
                *(__nv_bfloat162*)(zhp)     = hp0;
                *(__nv_bfloat162*)(zhp + 2) = hp1;
                *(__nv_bfloat162*)(zlp)     = lp0;
                *(__nv_bfloat162*)(zlp + 2) = lp1;
            }
        }
        {
            const uint4* gh = (const uint4*)(phase == 0 ? wl_hi : wr_hi);
            const uint4* gl = (const uint4*)(phase == 0 ? wl_lo : wr_lo);
            for (int i = t; i < 2048; i += 256) {
                int j = i >> 4, kc = i & 15;
                uint32_t off = ((uint32_t)(j * ZSTRIDE + kc * 8)) * 2;
                *(uint4*)(smem + OFF_WH + off) = gh[i];
                *(uint4*)(smem + OFF_WL + off) = gl[i];
            }
        }
        __syncthreads();

        const uint32_t zh_a = sbase + OFF_ZH + aoff;
        const uint32_t wh_b = sbase + OFF_WH + boff;

#pragma unroll
        for (int ks = 0; ks < 8; ks++) {
            uint32_t azh[2][4], azl[2][4], bh[2][4], bl[2][4];
#pragma unroll
            for (int f = 0; f < 2; f++) {
                uint32_t a = zh_a + ks * 32 + f * (16 * ZSTRIDE * 2);
                LDMX4(azh[f], a);
                LDMX4(azl[f], a + ZT_B);
            }
#pragma unroll
            for (int q = 0; q < 2; q++) {
                uint32_t a = wh_b + ks * 32 + q * (16 * ZSTRIDE * 2);
                LDMX4(bh[q], a);
                LDMX4(bl[q], a + WT_B);
            }
#pragma unroll
            for (int f = 0; f < 2; f++)
#pragma unroll
                for (int j = 0; j < 4; j++) {
                    const int q = j >> 1, s = (j & 1) * 2;
                    MMA16816(acc[f][j], azh[f], bh[q][s], bh[q][s + 1]);
                    MMA16816(acc[f][j], azl[f], bh[q][s], bh[q][s + 1]);
                    MMA16816(acc[f][j], azh[f], bl[q][s], bl[q][s + 1]);
                }
        }
        __syncthreads();
    }

    // epilogue: acc -> f32 staging in dead W region; skip-sum from z tiles.
    float* sh = (float*)(smem + OFF_WH);
#pragma unroll
    for (int f = 0; f < 2; f++) {
        int row = r0 + f * 16 + (lane >> 2);
        int col = wn * 32 + (lane & 3) * 2;
#pragma unroll
        for (int j = 0; j < 4; j++) {
            int c = col + j * 8;
            sh[row * HSTRIDE + c]           = acc[f][j][0];
            sh[row * HSTRIDE + c + 1]       = acc[f][j][1];
            sh[(row + 8) * HSTRIDE + c]     = acc[f][j][2];
            sh[(row + 8) * HSTRIDE + c + 1] = acc[f][j][3];
        }
    }
    __syncthreads();

    {
        const int row = t >> 2;
        const int qd  = t & 3;
        const int c0  = qd * 32;
        float ssq = 0.0f;
        float h[32];
#pragma unroll
        for (int c = 0; c < 32; c++) {
            float v = sh[row * HSTRIDE + c0 + c] + sbias[c0 + c];
            if (do_relu) v = fmaxf(v, 0.0f);
            h[c] = v;
            ssq += v * v;
        }
        ssq += __shfl_xor_sync(0xffffffffu, ssq, 1);
        ssq += __shfl_xor_sync(0xffffffffu, ssq, 2);
        float sc = 1.0f / fmaxf(sqrtf(ssq), 1e-12f);

        int node = tile + row;
        if (node < n) {
            float4* xo = (float4*)(xout + (size_t)node * DIM + c0);
            __half* xho = xh + (size_t)node * DIM + c0;
            const __nv_bfloat16* zhr = zh + row * ZSTRIDE + c0;
            const __nv_bfloat16* zlr = zl + row * ZSTRIDE + c0;
#pragma unroll
            for (int q = 0; q < 8; q++) {
                float4 o;
                o.x = __bfloat162float(zhr[q * 4 + 0]) + __bfloat162float(zlr[q * 4 + 0]) + h[q * 4 + 0] * sc;
                o.y = __bfloat162float(zhr[q * 4 + 1]) + __bfloat162float(zlr[q * 4 + 1]) + h[q * 4 + 1] * sc;
                o.z = __bfloat162float(zhr[q * 4 + 2]) + __bfloat162float(zlr[q * 4 + 2]) + h[q * 4 + 2] * sc;
                o.w = __bfloat162float(zhr[q * 4 + 3]) + __bfloat162float(zlr[q * 4 + 3]) + h[q * 4 + 3] * sc;
                xo[q] = o;
                if (write_h) {
                    __half2 p0 = __floats2half2_rn(o.x, o.y);
                    __half2 p1 = __floats2half2_rn(o.z, o.w);
                    uint2 pk;
                    pk.x = *(uint32_t*)&p0;
                    pk.y = *(uint32_t*)&p1;
                    *(uint2*)(xho + q * 4) = pk;
                }
            }
        }
    }
}

// ---------------------------------------------------------------------------
extern "C" void kernel_launch(void* const* d_in, const int* in_sizes, int n_in,
                              void* d_out, int out_size) {
    const float* x_gene  = (const float*)d_in[0];
    const float* x_dis   = (const float*)d_in[1];
    const float* Wl      = (const float*)d_in[2];
    const float* Wr      = (const float*)d_in[3];
    const float* b       = (const float*)d_in[4];
    const int*   src_g2d = (const int*)d_in[5];
    const int*   dst_g2d = (const int*)d_in[6];
    const int*   src_d2g = (const int*)d_in[7];
    const int*   dst_d2g = (const int*)d_in[8];

    const int n_gene = in_sizes[0] / DIM;
    const int n_dis  = in_sizes[1] / DIM;
    const int E1 = in_sizes[5];
    const int E2 = in_sizes[7];

    float *agg_d, *agg_g;
    __half *xh_g, *xh_d;
    int *cnt_d, *cnt_g, *off_d, *off_g, *cur_d, *cur_g, *csr_g2d, *csr_d2g;
    int *tmp, *part;
    __nv_bfloat16* wimg;
    cudaGetSymbolAddress((void**)&agg_d, g_agg_d);
    cudaGetSymbolAddress((void**)&agg_g, g_agg_g);
    cudaGetSymbolAddress((void**)&xh_g, g_xh_g);
    cudaGetSymbolAddress((void**)&xh_d, g_xh_d);
    cudaGetSymbolAddress((void**)&cnt_d, g_cnt_d);
    cudaGetSymbolAddress((void**)&cnt_g, g_cnt_g);
    cudaGetSymbolAddress((void**)&off_d, g_off_d);
    cudaGetSymbolAddress((void**)&off_g, g_off_g);
    cudaGetSymbolAddress((void**)&cur_d, g_cur_d);
    cudaGetSymbolAddress((void**)&cur_g, g_cur_g);
    cudaGetSymbolAddress((void**)&csr_g2d, g_csr_g2d);
    cudaGetSymbolAddress((void**)&csr_d2g, g_csr_d2g);
    cudaGetSymbolAddress((void**)&tmp, g_tmp);
    cudaGetSymbolAddress((void**)&part, g_part);
    cudaGetSymbolAddress((void**)&wimg, g_wimg);

    float* xg = (float*)d_out;
    float* xd = xg + (size_t)n_gene * DIM;

    prep_w_kernel<<<8, 256>>>(Wl, Wr);
    prep_xh_kernel<<<1024, 256>>>(x_gene, xh_g, (size_t)n_gene * DIM,
                                  x_dis, xh_d, (size_t)n_dis * DIM);

    // ---- CSR build ----
    const int n_tot = n_dis + n_gene;
    const int nz = (n_gene > n_dis ? n_gene : n_dis);
    const int nb_scan = (n_tot + SCAN_TILE - 1) / SCAN_TILE;
    zero2_kernel<<<(nz + 255) / 256, 256>>>(cnt_d, n_dis, cnt_g, n_gene);
    count2_kernel<<<(E1 + E2 + 255) / 256, 256>>>(dst_g2d, cnt_d, E1, dst_d2g, cnt_g, E2);
    scan_p1_kernel<<<nb_scan, 1024>>>(cnt_d, n_dis, cnt_g, n_gene, tmp, part);
    scan_p3_kernel<<<(n_tot + 255) / 256, 256>>>(tmp, part, nb_scan,
                                                 off_d, cur_d, n_dis,
                                                 off_g, cur_g, n_gene, E1, E2);
    fill2_kernel<<<(E1 + E2 + 255) / 256, 256>>>(src_g2d, dst_g2d, cur_d, csr_g2d, E1,
                                                 src_d2g, dst_d2g, cur_g, csr_d2g, E2);

    cudaFuncSetAttribute(update_fused_kernel,
                         cudaFuncAttributeMaxDynamicSharedMemorySize, SMEM_TOT);

    const int nbd = (n_dis + TM - 1) / TM;
    const int nbg = (n_gene + TM - 1) / TM;
    const int pull_blocks = ((n_dis + n_gene) * 32 + 255) / 256;

    // ---- layer 0: pulls read fp16 mirrors of inputs; update writes fp32 + mirrors ----
    pull_fused_kernel<<<pull_blocks, 256>>>(xh_g, xh_d, agg_d, agg_g,
                                            csr_g2d, off_d, csr_d2g, off_g,
                                            n_dis, n_gene);
    update_fused_kernel<<<nbd + nbg, 256, SMEM_TOT>>>(
        agg_d, x_dis, xd, xh_d, n_dis, agg_g, x_gene, xg, xh_g, n_gene,
        wimg, b, 0, nbd, 1, 1);

    // ---- layer 1: pulls read layer-0 mirrors; update in place, no mirror write ----
    pull_fused_kernel<<<pull_blocks, 256>>>(xh_g, xh_d, agg_d, agg_g,
                                            csr_g2d, off_d, csr_d2g, off_g,
                                            n_dis, n_gene);
    update_fused_kernel<<<nbd + nbg, 256, SMEM_TOT>>>(
        agg_d, xd, xd, xh_d, n_dis, agg_g, xg, xg, xh_g, n_gene,
        wimg, b, 1, nbd, 0, 0);
}